// round 11
// baseline (speedup 1.0000x reference)
#include <cuda_runtime.h>
#include <math.h>

#define Bc 4
#define Nc 1024
#define Hc 8
#define Dc 64
#define BSc 32
#define NBc 32
#define STOP 16
#define SCALE 0.125f
#define VROW 68   // floats per vT row: 64 keys + 4 pad (17x16B -> conflict-free LDS.128)

typedef unsigned long long u64;

__device__ float g_kcmp[Bc*NBc*Hc*Dc];
__device__ float g_vcmp[Bc*NBc*Hc*Dc];

__device__ __forceinline__ float siluf(float s) {
    return s / (1.f + __expf(-s));
}
__device__ __forceinline__ u64 ffma2(u64 a, u64 b, u64 c) {
    u64 d;
    asm("fma.rn.f32x2 %0, %1, %2, %3;" : "=l"(d) : "l"(a), "l"(b), "l"(c));
    return d;
}
__device__ __forceinline__ float2 u2f2(u64 u) {
    float2 f;
    asm("mov.b64 {%0, %1}, %2;" : "=f"(f.x), "=f"(f.y) : "l"(u));
    return f;
}

__global__ void meanKV(const float* __restrict__ pk, const float* __restrict__ pv) {
    int blk = blockIdx.x;
    int b  = blk / (NBc*Hc);
    int kb = (blk / Hc) % NBc;
    int h  = blk % Hc;
    int d  = threadIdx.x;
    float sk = 0.f, sv = 0.f;
    int base = ((b*Nc + kb*BSc)*Hc + h)*Dc + d;
    #pragma unroll 8
    for (int j = 0; j < BSc; j++) {
        sk += pk[base + j*Hc*Dc];
        sv += pv[base + j*Hc*Dc];
    }
    int o = ((b*NBc + kb)*Hc + h)*Dc + d;
    g_kcmp[o] = sk * (1.f/BSc);
    g_vcmp[o] = sv * (1.f/BSc);
}

// CTA = (q_block, head, batch); 4 warps; warp w owns query rows {w+4*qi}, qi=0..7.
// V transposed in shared (vT[dim][key]) -> PV uses natural {p_j,p_j+1} pairs,
// zero dup movs. Lane owns dims (lane, lane+32), two pair-accumulators/query.
__global__ __launch_bounds__(128, 4) void hstu_main(
    const float* __restrict__ pq, const float* __restrict__ pk,
    const float* __restrict__ pvv, const float* __restrict__ gate_w,
    const int* __restrict__ xoff, float* __restrict__ out)
{
    __shared__ __align__(16) float4 qsh4[32*16];     // 8KB
    __shared__ __align__(16) float4 kb4[16*64];      // 16KB K swizzled [d4][key^d4] (pair)
    __shared__ __align__(16) float  vT[64*VROW];     // 17KB V transposed [dim][key] (pair)
    __shared__ __align__(16) float  p_sh[32*32];     // 4KB p[row][key] (pre-gated)
    __shared__ int list[33];
    __shared__ int lcnt;
    __shared__ unsigned unionm;

    int qb = (NBc - 1) - blockIdx.x;   // heavy first
    int h = blockIdx.y, b = blockIdx.z;
    int len = xoff[b+1] - xoff[b];
    if (qb * BSc >= len) return;
    int nvalid = len - qb*BSc; if (nvalid > BSc) nvalid = BSc;
    int t0 = xoff[b];
    int tid = threadIdx.x, lane = tid & 31, w = tid >> 5;

    const ulonglong2* qshU = (const ulonglong2*)qsh4;
    const ulonglong2* kbU  = (const ulonglong2*)kb4;

    // ---- stage q + compressed K (coalesced) ----
    #pragma unroll
    for (int i = tid; i < 512; i += 128) {
        int r = i >> 4, c4 = i & 15;
        qsh4[r*16 + c4] = ((const float4*)(pq + ((b*Nc + qb*BSc + r)*Hc + h)*Dc))[c4];
        int gc = ((b*NBc + r)*Hc + h)*Dc;
        kb4[c4*64 + (r ^ c4)] = ((const float4*)(g_kcmp + gc))[c4];
    }
    // ---- stage compressed V transposed: lane=key, conflict-free STS.32 ----
    #pragma unroll
    for (int k = 0; k < 4; k++) {
        int c4 = k*4 + w;          // 0..15
        int row = lane;            // key 0..31
        float4 v = ((const float4*)(g_vcmp + ((b*NBc + row)*Hc + h)*Dc))[c4];
        int d0 = 4*c4;
        vT[(d0+0)*VROW + row] = v.x;
        vT[(d0+1)*VROW + row] = v.y;
        vT[(d0+2)*VROW + row] = v.z;
        vT[(d0+3)*VROW + row] = v.w;
    }
    if (tid == 0) unionm = 0;
    __syncthreads();

    u64 accA[8] = {0,0,0,0,0,0,0,0}, accB[8] = {0,0,0,0,0,0,0,0};
    float gsv[8];
    unsigned mysel[8];

    // ================= Phase A =================
    {
        const float* gw = gate_w + h*Dc*3;
        float gw0a = gw[(2*lane)*3 + 0], gw0b = gw[(2*lane+1)*3 + 0];
        float gw1a = gw[(2*lane)*3 + 1], gw1b = gw[(2*lane+1)*3 + 1];
        const float* qs = (const float*)qsh4;

        u64 sa[8] = {0,0,0,0,0,0,0,0};
        #pragma unroll
        for (int d4 = 0; d4 < 16; d4++) {
            ulonglong2 k0 = kbU[d4*64 + (lane ^ d4)];
            #pragma unroll
            for (int qi = 0; qi < 8; qi++) {
                ulonglong2 q = qshU[(w + qi*4)*16 + d4];
                sa[qi] = ffma2(q.x, k0.x, sa[qi]);
                sa[qi] = ffma2(q.y, k0.y, sa[qi]);
            }
        }
        bool causal = (lane <= qb);
        #pragma unroll
        for (int qi = 0; qi < 8; qi++) {
            int r = w + qi*4;
            float2 fa = u2f2(sa[qi]);
            float sc = (fa.x + fa.y) * SCALE;
            bool rowok = (r < nvalid);

            float q0 = qs[r*64 + 2*lane], q1 = qs[r*64 + 2*lane + 1];
            float pg0 = q0*gw0a + q1*gw0b;
            float pg1 = q0*gw1a + q1*gw1b;
            #pragma unroll
            for (int off = 16; off > 0; off >>= 1) {
                pg0 += __shfl_xor_sync(0xffffffffu, pg0, off);
                pg1 += __shfl_xor_sync(0xffffffffu, pg1, off);
            }
            float gcv = 1.f / (1.f + __expf(-pg0));
            gsv[qi]   = 1.f / (1.f + __expf(-pg1));

            p_sh[r*32 + lane] = (causal && rowok) ? siluf(sc) * gcv : 0.f;

            unsigned sel;
            if (!rowok) {
                sel = 0u;
            } else if (qb < STOP) {
                sel = (1u << (qb + 1)) - 1u;
            } else {
                unsigned ub = __float_as_uint(sc);
                unsigned u = ((int)ub < 0) ? ~ub : (ub | 0x80000000u);
                if (!causal) u = 0u;
                unsigned T = 0u;
                #pragma unroll
                for (int bit = 31; bit >= 0; --bit) {
                    unsigned cand = T | (1u << bit);
                    unsigned bal = __ballot_sync(0xffffffffu, u >= cand);
                    if (__popc(bal) >= STOP) T = cand;
                }
                unsigned gt = __ballot_sync(0xffffffffu, u > T);
                unsigned eq = __ballot_sync(0xffffffffu, u == T);
                int need = STOP - __popc(gt);
                bool take = ((eq >> lane) & 1u) &&
                            (__popc(eq & ((1u << lane) - 1u)) < need);
                unsigned eqt = __ballot_sync(0xffffffffu, take);
                sel = gt | eqt;
            }
            mysel[qi] = sel;
        }
        __syncwarp();
        unsigned wsel0 = 0;
        #pragma unroll
        for (int qi = 0; qi < 8; qi++) wsel0 |= mysel[qi];
        if (lane == 0) atomicOr(&unionm, wsel0);

        // compressed PV: natural key-pairs, no dups
        int j4hi = qb >> 2;
        for (int j4 = 0; j4 <= j4hi; j4++) {
            ulonglong2 vA = *(const ulonglong2*)&vT[lane*VROW + 4*j4];
            ulonglong2 vB = *(const ulonglong2*)&vT[(lane+32)*VROW + 4*j4];
            #pragma unroll
            for (int qi = 0; qi < 8; qi++) {
                ulonglong2 pp = *(const ulonglong2*)&p_sh[(w + qi*4)*32 + 4*j4];
                accA[qi] = ffma2(pp.x, vA.x, accA[qi]);
                accA[qi] = ffma2(pp.y, vA.y, accA[qi]);
                accB[qi] = ffma2(pp.x, vB.x, accB[qi]);
                accB[qi] = ffma2(pp.y, vB.y, accB[qi]);
            }
        }
    }
    unsigned wsel = 0;
    #pragma unroll
    for (int qi = 0; qi < 8; qi++) wsel |= mysel[qi];
    __syncthreads();
    unsigned um = unionm;
    if (tid == 0) {
        int c = 0;
        for (int kb = 0; kb <= qb; kb++)
            if ((um >> kb) & 1u) list[c++] = kb;
        lcnt = c;
    }
    __syncthreads();
    int cnt = lcnt;

    // ================= Phase B: paired 64-key tiles =================
    for (int it = 0; it < cnt; it += 2) {
        int kb0 = list[it];
        bool has1 = (it + 1 < cnt);
        int kb1 = has1 ? list[it + 1] : kb0;

        // K staging (coalesced, swizzled)
        #pragma unroll
        for (int i = tid; i < 512; i += 128) {
            int row = i >> 4, c4 = i & 15;
            int g0 = ((b*Nc + kb0*BSc + row)*Hc + h)*Dc;
            int g1 = ((b*Nc + kb1*BSc + row)*Hc + h)*Dc;
            kb4[c4*64 + (row ^ c4)]        = ((const float4*)(pk + g0))[c4];
            kb4[c4*64 + ((row + 32) ^ c4)] = ((const float4*)(pk + g1))[c4];
        }
        // V staging transposed (lane=key, conflict-free STS.32)
        #pragma unroll
        for (int k = 0; k < 4; k++) {
            int c4 = k*4 + w;
            int row = lane;
            float4 v0 = ((const float4*)(pvv + ((b*Nc + kb0*BSc + row)*Hc + h)*Dc))[c4];
            float4 v1 = ((const float4*)(pvv + ((b*Nc + kb1*BSc + row)*Hc + h)*Dc))[c4];
            int d0 = 4*c4;
            vT[(d0+0)*VROW + row] = v0.x;
            vT[(d0+1)*VROW + row] = v0.y;
            vT[(d0+2)*VROW + row] = v0.z;
            vT[(d0+3)*VROW + row] = v0.w;
            vT[(d0+0)*VROW + 32 + row] = v1.x;
            vT[(d0+1)*VROW + 32 + row] = v1.y;
            vT[(d0+2)*VROW + 32 + row] = v1.z;
            vT[(d0+3)*VROW + 32 + row] = v1.w;
        }
        __syncthreads();

        bool need0 = (wsel >> kb0) & 1u;
        bool need1 = has1 && ((wsel >> kb1) & 1u);
        if (need0 | need1) {
            u64 s0[8] = {0,0,0,0,0,0,0,0}, s1[8] = {0,0,0,0,0,0,0,0};
            #pragma unroll
            for (int d4 = 0; d4 < 16; d4++) {
                ulonglong2 k0 = kbU[d4*64 + (lane ^ d4)];
                ulonglong2 k1 = kbU[d4*64 + ((lane + 32) ^ d4)];
                #pragma unroll
                for (int qi = 0; qi < 8; qi++) {
                    ulonglong2 q = qshU[(w + qi*4)*16 + d4];
                    s0[qi] = ffma2(q.x, k0.x, s0[qi]);
                    s0[qi] = ffma2(q.y, k0.y, s0[qi]);
                    s1[qi] = ffma2(q.x, k1.x, s1[qi]);
                    s1[qi] = ffma2(q.y, k1.y, s1[qi]);
                }
            }
            // ---- tile 0 (keys 0..31 of pair) ----
            if (need0) {
                #pragma unroll
                for (int qi = 0; qi < 8; qi++) {
                    int r = w + qi*4;
                    int jmax = (kb0 == qb) ? r : 31;
                    bool u0 = ((mysel[qi] >> kb0) & 1u) && (lane <= jmax);
                    float2 f0 = u2f2(s0[qi]);
                    p_sh[r*32 + lane] = u0 ? siluf((f0.x + f0.y)*SCALE) * gsv[qi] : 0.f;
                }
                __syncwarp();
                #pragma unroll
                for (int j4 = 0; j4 < 8; j4++) {
                    ulonglong2 vA = *(const ulonglong2*)&vT[lane*VROW + 4*j4];
                    ulonglong2 vB = *(const ulonglong2*)&vT[(lane+32)*VROW + 4*j4];
                    #pragma unroll
                    for (int qi = 0; qi < 8; qi++) {
                        ulonglong2 pp = *(const ulonglong2*)&p_sh[(w + qi*4)*32 + 4*j4];
                        accA[qi] = ffma2(pp.x, vA.x, accA[qi]);
                        accA[qi] = ffma2(pp.y, vA.y, accA[qi]);
                        accB[qi] = ffma2(pp.x, vB.x, accB[qi]);
                        accB[qi] = ffma2(pp.y, vB.y, accB[qi]);
                    }
                }
                __syncwarp();
            }
            // ---- tile 1 (keys 32..63 of pair) ----
            if (need1) {
                #pragma unroll
                for (int qi = 0; qi < 8; qi++) {
                    int r = w + qi*4;
                    int jmax = (kb1 == qb) ? r : 31;
                    bool u1 = ((mysel[qi] >> kb1) & 1u) && (lane <= jmax);
                    float2 f1 = u2f2(s1[qi]);
                    p_sh[r*32 + lane] = u1 ? siluf((f1.x + f1.y)*SCALE) * gsv[qi] : 0.f;
                }
                __syncwarp();
                #pragma unroll
                for (int j4 = 0; j4 < 8; j4++) {
                    ulonglong2 vA = *(const ulonglong2*)&vT[lane*VROW + 32 + 4*j4];
                    ulonglong2 vB = *(const ulonglong2*)&vT[(lane+32)*VROW + 32 + 4*j4];
                    #pragma unroll
                    for (int qi = 0; qi < 8; qi++) {
                        ulonglong2 pp = *(const ulonglong2*)&p_sh[(w + qi*4)*32 + 4*j4];
                        accA[qi] = ffma2(pp.x, vA.x, accA[qi]);
                        accA[qi] = ffma2(pp.y, vA.y, accA[qi]);
                        accB[qi] = ffma2(pp.x, vB.x, accB[qi]);
                        accB[qi] = ffma2(pp.y, vB.y, accB[qi]);
                    }
                }
            }
        }
        __syncthreads();
    }

    // ================= Output (already gated; lane owns dims lane, lane+32) ====
    #pragma unroll
    for (int qi = 0; qi < 8; qi++) {
        int r = w + qi*4;
        if (r >= nvalid) continue;   // warp-uniform
        float2 a = u2f2(accA[qi]);
        float2 bb = u2f2(accB[qi]);
        int n = qb*BSc + r;
        int o = ((t0 + n)*Hc + h)*Dc;
        out[o + lane]      = a.x + a.y;
        out[o + lane + 32] = bb.x + bb.y;
    }
}

extern "C" void kernel_launch(void* const* d_in, const int* in_sizes, int n_in,
                              void* d_out, int out_size) {
    const float* pq   = (const float*)d_in[4];
    const float* pk   = (const float*)d_in[5];
    const float* pv   = (const float*)d_in[6];
    const int*   xoff = (const int*)d_in[7];
    const float* gw   = (const float*)d_in[8];
    float* out = (float*)d_out;

    meanKV<<<Bc*NBc*Hc, 64>>>(pk, pv);
    dim3 grid(NBc, Hc, Bc);
    hstu_main<<<grid, 128>>>(pq, pk, pv, gw, xoff, out);
}

// round 12
// speedup vs baseline: 1.1916x; 1.1916x over previous
#include <cuda_runtime.h>
#include <math.h>

#define Bc 4
#define Nc 1024
#define Hc 8
#define Dc 64
#define BSc 32
#define NBc 32
#define STOP 16
#define SCALE 0.125f

typedef unsigned long long u64;

__device__ float g_kcmp[Bc*NBc*Hc*Dc];
__device__ float g_vcmp[Bc*NBc*Hc*Dc];

__device__ __forceinline__ float siluf(float s) {
    return s / (1.f + __expf(-s));
}
__device__ __forceinline__ u64 ffma2(u64 a, u64 b, u64 c) {
    u64 d;
    asm("fma.rn.f32x2 %0, %1, %2, %3;" : "=l"(d) : "l"(a), "l"(b), "l"(c));
    return d;
}
__device__ __forceinline__ u64 dup2(float x) {
    u64 r;
    asm("mov.b64 %0, {%1, %1};" : "=l"(r) : "f"(x));
    return r;
}
__device__ __forceinline__ float2 u2f2(u64 u) {
    float2 f;
    asm("mov.b64 {%0, %1}, %2;" : "=f"(f.x), "=f"(f.y) : "l"(u));
    return f;
}

__global__ void meanKV(const float* __restrict__ pk, const float* __restrict__ pv) {
    int blk = blockIdx.x;
    int b  = blk / (NBc*Hc);
    int kb = (blk / Hc) % NBc;
    int h  = blk % Hc;
    int d  = threadIdx.x;
    float sk = 0.f, sv = 0.f;
    int base = ((b*Nc + kb*BSc)*Hc + h)*Dc + d;
    #pragma unroll 8
    for (int j = 0; j < BSc; j++) {
        sk += pk[base + j*Hc*Dc];
        sv += pv[base + j*Hc*Dc];
    }
    int o = ((b*NBc + kb)*Hc + h)*Dc + d;
    g_kcmp[o] = sk * (1.f/BSc);
    g_vcmp[o] = sv * (1.f/BSc);
}

// CTA = (q_block, head, batch); 4 warps; warp w owns query rows {w+4*qi}, qi=0..7.
// Phase B: paired 64-key tiles; next pair's K prefetched into registers while
// current pair computes (software pipeline, no extra smem/barriers).
__global__ __launch_bounds__(128, 4) void hstu_main(
    const float* __restrict__ pq, const float* __restrict__ pk,
    const float* __restrict__ pvv, const float* __restrict__ gate_w,
    const int* __restrict__ xoff, float* __restrict__ out)
{
    __shared__ __align__(16) float4 qsh4[32*16];   // 8KB
    __shared__ __align__(16) float4 kb4[16*64];    // 16KB K swizzled [d4][key^d4] (pair)
    __shared__ __align__(16) float4 vb4[64*16];    // 16KB V [key][d4] (pair)
    __shared__ __align__(16) float  p_sh[32*32];   // 4KB p[row][key] (pre-gated)
    __shared__ int list[33];
    __shared__ int lcnt;
    __shared__ unsigned unionm;

    int qb = (NBc - 1) - blockIdx.x;   // heavy first
    int h = blockIdx.y, b = blockIdx.z;
    int len = xoff[b+1] - xoff[b];
    if (qb * BSc >= len) return;
    int nvalid = len - qb*BSc; if (nvalid > BSc) nvalid = BSc;
    int t0 = xoff[b];
    int tid = threadIdx.x, lane = tid & 31, w = tid >> 5;

    const ulonglong2* qshU = (const ulonglong2*)qsh4;
    const ulonglong2* kbU  = (const ulonglong2*)kb4;
    const u64*        vbU  = (const u64*)vb4;
    const float4*     p4   = (const float4*)p_sh;

    // ---- stage q + compressed K/V ----
    #pragma unroll
    for (int i = tid; i < 512; i += 128) {
        int r = i >> 4, c4 = i & 15;
        qsh4[r*16 + c4] = ((const float4*)(pq + ((b*Nc + qb*BSc + r)*Hc + h)*Dc))[c4];
        int gc = ((b*NBc + r)*Hc + h)*Dc;
        kb4[c4*64 + (r ^ c4)] = ((const float4*)(g_kcmp + gc))[c4];
        vb4[r*16 + c4]        = ((const float4*)(g_vcmp + gc))[c4];
    }
    if (tid == 0) unionm = 0;
    __syncthreads();

    u64 acc[8] = {0,0,0,0,0,0,0,0};
    float gsv[8];
    unsigned mysel[8];

    // ================= Phase A =================
    {
        const float* gw = gate_w + h*Dc*3;
        float gw0a = gw[(2*lane)*3 + 0], gw0b = gw[(2*lane+1)*3 + 0];
        float gw1a = gw[(2*lane)*3 + 1], gw1b = gw[(2*lane+1)*3 + 1];
        const float* qs = (const float*)qsh4;

        u64 sa[8] = {0,0,0,0,0,0,0,0};
        #pragma unroll
        for (int d4 = 0; d4 < 16; d4++) {
            ulonglong2 k0 = kbU[d4*64 + (lane ^ d4)];
            #pragma unroll
            for (int qi = 0; qi < 8; qi++) {
                ulonglong2 q = qshU[(w + qi*4)*16 + d4];
                sa[qi] = ffma2(q.x, k0.x, sa[qi]);
                sa[qi] = ffma2(q.y, k0.y, sa[qi]);
            }
        }
        bool causal = (lane <= qb);
        #pragma unroll
        for (int qi = 0; qi < 8; qi++) {
            int r = w + qi*4;
            float2 fa = u2f2(sa[qi]);
            float sc = (fa.x + fa.y) * SCALE;
            bool rowok = (r < nvalid);

            float q0 = qs[r*64 + 2*lane], q1 = qs[r*64 + 2*lane + 1];
            float pg0 = q0*gw0a + q1*gw0b;
            float pg1 = q0*gw1a + q1*gw1b;
            #pragma unroll
            for (int off = 16; off > 0; off >>= 1) {
                pg0 += __shfl_xor_sync(0xffffffffu, pg0, off);
                pg1 += __shfl_xor_sync(0xffffffffu, pg1, off);
            }
            float gcv = 1.f / (1.f + __expf(-pg0));
            gsv[qi]   = 1.f / (1.f + __expf(-pg1));

            p_sh[r*32 + lane] = (causal && rowok) ? siluf(sc) * gcv : 0.f;

            unsigned sel;
            if (!rowok) {
                sel = 0u;
            } else if (qb < STOP) {
                sel = (1u << (qb + 1)) - 1u;
            } else {
                unsigned ub = __float_as_uint(sc);
                unsigned u = ((int)ub < 0) ? ~ub : (ub | 0x80000000u);
                if (!causal) u = 0u;
                unsigned T = 0u;
                #pragma unroll
                for (int bit = 31; bit >= 0; --bit) {
                    unsigned cand = T | (1u << bit);
                    unsigned bal = __ballot_sync(0xffffffffu, u >= cand);
                    if (__popc(bal) >= STOP) T = cand;
                }
                unsigned gt = __ballot_sync(0xffffffffu, u > T);
                unsigned eq = __ballot_sync(0xffffffffu, u == T);
                int need = STOP - __popc(gt);
                bool take = ((eq >> lane) & 1u) &&
                            (__popc(eq & ((1u << lane) - 1u)) < need);
                unsigned eqt = __ballot_sync(0xffffffffu, take);
                sel = gt | eqt;
            }
            mysel[qi] = sel;
        }
        __syncwarp();
        unsigned wsel0 = 0;
        #pragma unroll
        for (int qi = 0; qi < 8; qi++) wsel0 |= mysel[qi];
        if (lane == 0) atomicOr(&unionm, wsel0);

        // compressed PV (keys 0..qb)
        int j4hi = qb >> 2;
        for (int j4 = 0; j4 <= j4hi; j4++) {
            u64 v[4];
            #pragma unroll
            for (int jj = 0; jj < 4; jj++) v[jj] = vbU[(j4*4 + jj)*32 + lane];
            #pragma unroll
            for (int qi = 0; qi < 8; qi++) {
                float4 pb = p4[(w + qi*4)*8 + j4];
                acc[qi] = ffma2(dup2(pb.x), v[0], acc[qi]);
                acc[qi] = ffma2(dup2(pb.y), v[1], acc[qi]);
                acc[qi] = ffma2(dup2(pb.z), v[2], acc[qi]);
                acc[qi] = ffma2(dup2(pb.w), v[3], acc[qi]);
            }
        }
    }
    unsigned wsel = 0;
    #pragma unroll
    for (int qi = 0; qi < 8; qi++) wsel |= mysel[qi];
    __syncthreads();
    unsigned um = unionm;
    if (tid == 0) {
        int c = 0;
        for (int kb = 0; kb <= qb; kb++)
            if ((um >> kb) & 1u) list[c++] = kb;
        lcnt = c;
    }
    __syncthreads();
    int cnt = lcnt;

    // ================= Phase B: paired tiles with K register prefetch ========
    int c4s = tid & 15, r0s = tid >> 4;     // staging coords (rows r0s + 8s)
    float4 rk0[4], rk1[4];                  // prefetched K pair (32 regs)

    if (cnt > 0) {
        int kb0 = list[0];
        int kb1 = (1 < cnt) ? list[1] : kb0;
        #pragma unroll
        for (int s = 0; s < 4; s++) {
            int row = r0s + s*8;
            rk0[s] = ((const float4*)(pk + ((b*Nc + kb0*BSc + row)*Hc + h)*Dc))[c4s];
            rk1[s] = ((const float4*)(pk + ((b*Nc + kb1*BSc + row)*Hc + h)*Dc))[c4s];
        }
    }

    for (int it = 0; it < cnt; it += 2) {
        int kb0 = list[it];
        bool has1 = (it + 1 < cnt);
        int kb1 = has1 ? list[it + 1] : kb0;

        // store prefetched K; stage V inline
        #pragma unroll
        for (int s = 0; s < 4; s++) {
            int row = r0s + s*8;
            kb4[c4s*64 + (row ^ c4s)]        = rk0[s];
            kb4[c4s*64 + ((row + 32) ^ c4s)] = rk1[s];
            vb4[row*16 + c4s]        = ((const float4*)(pvv + ((b*Nc + kb0*BSc + row)*Hc + h)*Dc))[c4s];
            vb4[(row + 32)*16 + c4s] = ((const float4*)(pvv + ((b*Nc + kb1*BSc + row)*Hc + h)*Dc))[c4s];
        }
        __syncthreads();

        // prefetch next pair's K into regs (flies during compute below)
        {
            int nx = it + 2;
            if (nx < cnt) {
                int nb0 = list[nx];
                int nb1 = (nx + 1 < cnt) ? list[nx + 1] : nb0;
                #pragma unroll
                for (int s = 0; s < 4; s++) {
                    int row = r0s + s*8;
                    rk0[s] = ((const float4*)(pk + ((b*Nc + nb0*BSc + row)*Hc + h)*Dc))[c4s];
                    rk1[s] = ((const float4*)(pk + ((b*Nc + nb1*BSc + row)*Hc + h)*Dc))[c4s];
                }
            }
        }

        bool need0 = (wsel >> kb0) & 1u;
        bool need1 = has1 && ((wsel >> kb1) & 1u);
        if (need0 | need1) {
            u64 s0[8] = {0,0,0,0,0,0,0,0}, s1[8] = {0,0,0,0,0,0,0,0};
            #pragma unroll
            for (int d4 = 0; d4 < 16; d4++) {
                ulonglong2 k0 = kbU[d4*64 + (lane ^ d4)];
                ulonglong2 k1 = kbU[d4*64 + ((lane + 32) ^ d4)];
                #pragma unroll
                for (int qi = 0; qi < 8; qi++) {
                    ulonglong2 q = qshU[(w + qi*4)*16 + d4];
                    s0[qi] = ffma2(q.x, k0.x, s0[qi]);
                    s0[qi] = ffma2(q.y, k0.y, s0[qi]);
                    s1[qi] = ffma2(q.x, k1.x, s1[qi]);
                    s1[qi] = ffma2(q.y, k1.y, s1[qi]);
                }
            }
            // ---- tile 0 ----
            if (need0) {
                #pragma unroll
                for (int qi = 0; qi < 8; qi++) {
                    int r = w + qi*4;
                    int jmax = (kb0 == qb) ? r : 31;
                    bool u0 = ((mysel[qi] >> kb0) & 1u) && (lane <= jmax);
                    float2 f0 = u2f2(s0[qi]);
                    p_sh[r*32 + lane] = u0 ? siluf((f0.x + f0.y)*SCALE) * gsv[qi] : 0.f;
                }
                __syncwarp();
                #pragma unroll
                for (int j4 = 0; j4 < 8; j4++) {
                    u64 v[4];
                    #pragma unroll
                    for (int jj = 0; jj < 4; jj++) v[jj] = vbU[(j4*4 + jj)*32 + lane];
                    #pragma unroll
                    for (int qi = 0; qi < 8; qi++) {
                        float4 pb = p4[(w + qi*4)*8 + j4];
                        acc[qi] = ffma2(dup2(pb.x), v[0], acc[qi]);
                        acc[qi] = ffma2(dup2(pb.y), v[1], acc[qi]);
                        acc[qi] = ffma2(dup2(pb.z), v[2], acc[qi]);
                        acc[qi] = ffma2(dup2(pb.w), v[3], acc[qi]);
                    }
                }
                __syncwarp();
            }
            // ---- tile 1 ----
            if (need1) {
                #pragma unroll
                for (int qi = 0; qi < 8; qi++) {
                    int r = w + qi*4;
                    int jmax = (kb1 == qb) ? r : 31;
                    bool u1 = ((mysel[qi] >> kb1) & 1u) && (lane <= jmax);
                    float2 f1 = u2f2(s1[qi]);
                    p_sh[r*32 + lane] = u1 ? siluf((f1.x + f1.y)*SCALE) * gsv[qi] : 0.f;
                }
                __syncwarp();
                #pragma unroll
                for (int j4 = 0; j4 < 8; j4++) {
                    u64 v[4];
                    #pragma unroll
                    for (int jj = 0; jj < 4; jj++) v[jj] = vbU[(32 + j4*4 + jj)*32 + lane];
                    #pragma unroll
                    for (int qi = 0; qi < 8; qi++) {
                        float4 pb = p4[(w + qi*4)*8 + j4];
                        acc[qi] = ffma2(dup2(pb.x), v[0], acc[qi]);
                        acc[qi] = ffma2(dup2(pb.y), v[1], acc[qi]);
                        acc[qi] = ffma2(dup2(pb.z), v[2], acc[qi]);
                        acc[qi] = ffma2(dup2(pb.w), v[3], acc[qi]);
                    }
                }
            }
        }
        __syncthreads();
    }

    // ================= Output (already gated) =================
    #pragma unroll
    for (int qi = 0; qi < 8; qi++) {
        int r = w + qi*4;
        if (r >= nvalid) continue;   // warp-uniform
        float2 o2 = u2f2(acc[qi]);
        int n = qb*BSc + r;
        int o = ((t0 + n)*Hc + h)*Dc;
        *((float2*)(out + o) + lane) = o2;
    }
}

extern "C" void kernel_launch(void* const* d_in, const int* in_sizes, int n_in,
                              void* d_out, int out_size) {
    const float* pq   = (const float*)d_in[4];
    const float* pk   = (const float*)d_in[5];
    const float* pv   = (const float*)d_in[6];
    const int*   xoff = (const int*)d_in[7];
    const float* gw   = (const float*)d_in[8];
    float* out = (float*)d_out;

    meanKV<<<Bc*NBc*Hc, 64>>>(pk, pv);
    dim3 grid(NBc, Hc, Bc);
    hstu_main<<<grid, 128>>>(pq, pk, pv, gw, xoff, out);
}

// round 13
// speedup vs baseline: 1.4216x; 1.1930x over previous
#include <cuda_runtime.h>
#include <cuda_bf16.h>
#include <math.h>

#define Bc 4
#define Nc 1024
#define Hc 8
#define Dc 64
#define BSc 32
#define NBc 32
#define STOP 16
#define SCALE 0.125f
#define TOT (Bc*Nc*Hc*Dc)

// dynamic shared layout (bytes)
#define OFF_QHILO 0        // Phase B: qhi(4608)+qlo(4608); Phase A: kcmp fp32 (8192)
#define OFF_KHILO 9216     // Phase B: khi(9216)+klo(9216); Phase A: q fp32 (8192)
#define OFF_V     27648    // vb4 (16384)
#define OFF_P     44032    // p_sh 32x64 fp32 (8192)
#define SMEM_TOT  52224

typedef unsigned long long u64;
typedef unsigned int u32;

__device__ float g_kcmp[Bc*NBc*Hc*Dc];
__device__ float g_vcmp[Bc*NBc*Hc*Dc];
__device__ __nv_bfloat16 g_qhi[TOT], g_qlo[TOT], g_khi[TOT], g_klo[TOT];

__device__ __forceinline__ float siluf(float s) {
    return s / (1.f + __expf(-s));
}
__device__ __forceinline__ u64 ffma2(u64 a, u64 b, u64 c) {
    u64 d;
    asm("fma.rn.f32x2 %0, %1, %2, %3;" : "=l"(d) : "l"(a), "l"(b), "l"(c));
    return d;
}
__device__ __forceinline__ u64 dup2(float x) {
    u64 r;
    asm("mov.b64 %0, {%1, %1};" : "=l"(r) : "f"(x));
    return r;
}
__device__ __forceinline__ float2 u2f2(u64 u) {
    float2 f;
    asm("mov.b64 {%0, %1}, %2;" : "=f"(f.x), "=f"(f.y) : "l"(u));
    return f;
}
__device__ __forceinline__ void ldmx4(u32* a, u32 addr) {
    asm volatile("ldmatrix.sync.aligned.m8n8.x4.shared.b16 {%0,%1,%2,%3}, [%4];"
        : "=r"(a[0]), "=r"(a[1]), "=r"(a[2]), "=r"(a[3]) : "r"(addr));
}
__device__ __forceinline__ void ldmx2(u32* b, u32 addr) {
    asm volatile("ldmatrix.sync.aligned.m8n8.x2.shared.b16 {%0,%1}, [%2];"
        : "=r"(b[0]), "=r"(b[1]) : "r"(addr));
}
__device__ __forceinline__ void mma16816(float* c, const u32* a, const u32* b) {
    asm volatile("mma.sync.aligned.m16n8k16.row.col.f32.bf16.bf16.f32 "
        "{%0,%1,%2,%3},{%4,%5,%6,%7},{%8,%9},{%0,%1,%2,%3};"
        : "+f"(c[0]), "+f"(c[1]), "+f"(c[2]), "+f"(c[3])
        : "r"(a[0]), "r"(a[1]), "r"(a[2]), "r"(a[3]), "r"(b[0]), "r"(b[1]));
}

__global__ void meanKV(const float* __restrict__ pk, const float* __restrict__ pv) {
    int blk = blockIdx.x;
    int b  = blk / (NBc*Hc);
    int kb = (blk / Hc) % NBc;
    int h  = blk % Hc;
    int d  = threadIdx.x;
    float sk = 0.f, sv = 0.f;
    int base = ((b*Nc + kb*BSc)*Hc + h)*Dc + d;
    #pragma unroll 8
    for (int j = 0; j < BSc; j++) {
        sk += pk[base + j*Hc*Dc];
        sv += pv[base + j*Hc*Dc];
    }
    int o = ((b*NBc + kb)*Hc + h)*Dc + d;
    g_kcmp[o] = sk * (1.f/BSc);
    g_vcmp[o] = sv * (1.f/BSc);
}

// bf16 hi/lo split of q and K (hi + lo captures 16 mantissa bits)
__global__ void splitQK(const float* __restrict__ pq, const float* __restrict__ pk) {
    int i = blockIdx.x*256 + threadIdx.x;
    if (i < TOT) {
        float x = pq[i];
        __nv_bfloat16 h = __float2bfloat16(x);
        g_qhi[i] = h;
        g_qlo[i] = __float2bfloat16(x - __bfloat162float(h));
        float y = pk[i];
        __nv_bfloat16 h2 = __float2bfloat16(y);
        g_khi[i] = h2;
        g_klo[i] = __float2bfloat16(y - __bfloat162float(h2));
    }
}

// CTA = (q_block, head, batch); 4 warps; warp w owns query rows {w+4*qi} for PV.
// Phase B QK on tensor cores (bf16 split, hh+hl+lh). PV scalar fp32 (ffma2).
__global__ __launch_bounds__(128, 4) void hstu_main(
    const float* __restrict__ pq, const float* __restrict__ pvv,
    const float* __restrict__ gate_w, const int* __restrict__ xoff,
    float* __restrict__ out)
{
    extern __shared__ __align__(16) char smem[];
    float*  qsA   = (float*) (smem + OFF_KHILO);   // Phase A q fp32
    float4* kcmpA = (float4*)(smem + OFF_QHILO);   // Phase A compressed K
    float4* vb4   = (float4*)(smem + OFF_V);
    float*  p_sh  = (float*) (smem + OFF_P);       // p[row][key0..63], pre-gated
    __shared__ int list[33];
    __shared__ int lcnt;
    __shared__ unsigned unionm;
    __shared__ unsigned selm_sh[32];
    __shared__ float gsv_sh[32];

    int qb = (NBc - 1) - blockIdx.x;   // heavy first
    int h = blockIdx.y, b = blockIdx.z;
    int len = xoff[b+1] - xoff[b];
    if (qb * BSc >= len) return;
    int nvalid = len - qb*BSc; if (nvalid > BSc) nvalid = BSc;
    int t0 = xoff[b];
    int tid = threadIdx.x, lane = tid & 31, w = tid >> 5;

    const ulonglong2* qshU = (const ulonglong2*)qsA;
    const ulonglong2* kcU  = (const ulonglong2*)kcmpA;
    const u64*        vbU  = (const u64*)vb4;
    const float4*     p4   = (const float4*)p_sh;
    u32 sbase = (u32)__cvta_generic_to_shared(smem);

    // ---- Phase A staging: q fp32, compressed K (swizzled, 32 keys), compressed V ----
    #pragma unroll
    for (int i = tid; i < 512; i += 128) {
        int r = i >> 4, c4 = i & 15;
        ((float4*)qsA)[r*16 + c4] = ((const float4*)(pq + ((b*Nc + qb*BSc + r)*Hc + h)*Dc))[c4];
        int gc = ((b*NBc + r)*Hc + h)*Dc;
        kcmpA[c4*32 + (r ^ c4)] = ((const float4*)(g_kcmp + gc))[c4];
        vb4[r*16 + c4]          = ((const float4*)(g_vcmp + gc))[c4];
    }
    if (tid == 0) unionm = 0;
    __syncthreads();

    u64 acc[8] = {0,0,0,0,0,0,0,0};
    unsigned wsel = 0;

    // ================= Phase A (scalar fp32, exact top-k) =================
    {
        const float* gw = gate_w + h*Dc*3;
        float gw0a = gw[(2*lane)*3 + 0], gw0b = gw[(2*lane+1)*3 + 0];
        float gw1a = gw[(2*lane)*3 + 1], gw1b = gw[(2*lane+1)*3 + 1];

        u64 sa[8] = {0,0,0,0,0,0,0,0};
        #pragma unroll
        for (int d4 = 0; d4 < 16; d4++) {
            ulonglong2 k0 = kcU[d4*32 + (lane ^ d4)];
            #pragma unroll
            for (int qi = 0; qi < 8; qi++) {
                ulonglong2 q = qshU[(w + qi*4)*16 + d4];
                sa[qi] = ffma2(q.x, k0.x, sa[qi]);
                sa[qi] = ffma2(q.y, k0.y, sa[qi]);
            }
        }
        bool causal = (lane <= qb);
        #pragma unroll
        for (int qi = 0; qi < 8; qi++) {
            int r = w + qi*4;
            float2 fa = u2f2(sa[qi]);
            float sc = (fa.x + fa.y) * SCALE;
            bool rowok = (r < nvalid);

            float q0 = qsA[r*64 + 2*lane], q1 = qsA[r*64 + 2*lane + 1];
            float pg0 = q0*gw0a + q1*gw0b;
            float pg1 = q0*gw1a + q1*gw1b;
            #pragma unroll
            for (int off = 16; off > 0; off >>= 1) {
                pg0 += __shfl_xor_sync(0xffffffffu, pg0, off);
                pg1 += __shfl_xor_sync(0xffffffffu, pg1, off);
            }
            float gcv = 1.f / (1.f + __expf(-pg0));
            float gsvv = 1.f / (1.f + __expf(-pg1));

            p_sh[r*64 + lane] = (causal && rowok) ? siluf(sc) * gcv : 0.f;

            unsigned sel;
            if (!rowok) {
                sel = 0u;
            } else if (qb < STOP) {
                sel = (1u << (qb + 1)) - 1u;
            } else {
                unsigned ub = __float_as_uint(sc);
                unsigned u = ((int)ub < 0) ? ~ub : (ub | 0x80000000u);
                if (!causal) u = 0u;
                unsigned T = 0u;
                #pragma unroll
                for (int bit = 31; bit >= 0; --bit) {
                    unsigned cand = T | (1u << bit);
                    unsigned bal = __ballot_sync(0xffffffffu, u >= cand);
                    if (__popc(bal) >= STOP) T = cand;
                }
                unsigned gt = __ballot_sync(0xffffffffu, u > T);
                unsigned eq = __ballot_sync(0xffffffffu, u == T);
                int need = STOP - __popc(gt);
                bool take = ((eq >> lane) & 1u) &&
                            (__popc(eq & ((1u << lane) - 1u)) < need);
                unsigned eqt = __ballot_sync(0xffffffffu, take);
                sel = gt | eqt;
            }
            wsel |= sel;
            if (lane == 0) { selm_sh[r] = sel; gsv_sh[r] = gsvv; }
        }
        __syncwarp();
        if (lane == 0) atomicOr(&unionm, wsel);

        // compressed PV (keys 0..qb)
        int j4hi = qb >> 2;
        for (int j4 = 0; j4 <= j4hi; j4++) {
            u64 v[4];
            #pragma unroll
            for (int jj = 0; jj < 4; jj++) v[jj] = vbU[(j4*4 + jj)*32 + lane];
            #pragma unroll
            for (int qi = 0; qi < 8; qi++) {
                float4 pb = p4[(w + qi*4)*16 + j4];
                acc[qi] = ffma2(dup2(pb.x), v[0], acc[qi]);
                acc[qi] = ffma2(dup2(pb.y), v[1], acc[qi]);
                acc[qi] = ffma2(dup2(pb.z), v[2], acc[qi]);
                acc[qi] = ffma2(dup2(pb.w), v[3], acc[qi]);
            }
        }
    }
    __syncthreads();   // Phase A reads of kcmp/q/vcmp done
    unsigned um = unionm;
    if (tid == 0) {
        int c = 0;
        for (int kb = 0; kb <= qb; kb++)
            if ((um >> kb) & 1u) list[c++] = kb;
        lcnt = c;
    }

    // ---- stage q bf16 planes (overwrites kcmp region; safe after barrier) ----
    #pragma unroll
    for (int s = 0; s < 2; s++) {
        int i = tid + s*128;
        int row = i >> 3, c = i & 7;
        int gq = ((b*Nc + qb*BSc + row)*Hc + h)*Dc + c*8;
        *(float4*)(smem + OFF_QHILO + row*144 + c*16)        = *(const float4*)(g_qhi + gq);
        *(float4*)(smem + OFF_QHILO + 4608 + row*144 + c*16) = *(const float4*)(g_qlo + gq);
    }
    __syncthreads();
    int cnt = lcnt;

    // ================= Phase B =================
    int cst = tid & 7;            // K chunk (8 bf16 = 16B)
    int k0t = tid >> 3;           // base key (+16 per sweep)
    float4 rkhi[4], rklo[4];      // prefetched K pair planes

    auto k_ld = [&](int kb0, int kb1) {
        #pragma unroll
        for (int s = 0; s < 4; s++) {
            int key = k0t + s*16;
            int kbb = (key < 32) ? (kb0*BSc + key) : (kb1*BSc + key - 32);
            int g = ((b*Nc + kbb)*Hc + h)*Dc + cst*8;
            rkhi[s] = *(const float4*)(g_khi + g);
            rklo[s] = *(const float4*)(g_klo + g);
        }
    };

    if (cnt > 0) {
        int kb0 = list[0];
        int kb1 = (1 < cnt) ? list[1] : kb0;
        k_ld(kb0, kb1);
    }

    int r0s = tid >> 4, c4s = tid & 15;   // V staging coords
    u32 qhiA = sbase + OFF_QHILO, qloA = qhiA + 4608;
    u32 khiA = sbase + OFF_KHILO, kloA = khiA + 9216;
    int arow = ((lane >> 3) & 1)*8 + (lane & 7);
    int acol = (lane >> 4)*8;
    int brow = lane & 7;
    int bcol = ((lane >> 3) & 1)*8;
    int g4 = lane >> 2, t4 = lane & 3;

    for (int it = 0; it < cnt; it += 2) {
        int kb0 = list[it];
        bool has1 = (it + 1 < cnt);
        int kb1 = has1 ? list[it + 1] : kb0;

        // store prefetched K planes; stage V inline
        #pragma unroll
        for (int s = 0; s < 4; s++) {
            int key = k0t + s*16;
            *(float4*)(smem + OFF_KHILO + key*144 + cst*16)        = rkhi[s];
            *(float4*)(smem + OFF_KHILO + 9216 + key*144 + cst*16) = rklo[s];
        }
        #pragma unroll
        for (int s = 0; s < 4; s++) {
            int row = r0s + s*8;
            vb4[row*16 + c4s]        = ((const float4*)(pvv + ((b*Nc + kb0*BSc + row)*Hc + h)*Dc))[c4s];
            vb4[(row + 32)*16 + c4s] = ((const float4*)(pvv + ((b*Nc + kb1*BSc + row)*Hc + h)*Dc))[c4s];
        }
        __syncthreads();

        // prefetch next pair's K planes
        if (it + 2 < cnt) {
            int nb0 = list[it + 2];
            int nb1 = (it + 3 < cnt) ? list[it + 3] : nb0;
            k_ld(nb0, nb1);
        }

        // ---- QK via bf16-split MMA: warp w computes keys [16w,16w+16) x rows 0..31 ----
        float C[2][2][4];
        #pragma unroll
        for (int mt = 0; mt < 2; mt++)
            #pragma unroll
            for (int nt = 0; nt < 2; nt++)
                #pragma unroll
                for (int e = 0; e < 4; e++) C[mt][nt][e] = 0.f;

        #pragma unroll
        for (int ks = 0; ks < 4; ks++) {
            u32 ahi[2][4], alo[2][4];
            #pragma unroll
            for (int mt = 0; mt < 2; mt++) {
                u32 off = (u32)(((mt*16 + arow)*72 + ks*16 + acol)*2);
                ldmx4(ahi[mt], qhiA + off);
                ldmx4(alo[mt], qloA + off);
            }
            #pragma unroll
            for (int nt = 0; nt < 2; nt++) {
                int key0 = 16*w + 8*nt;
                u32 boff = (u32)(((key0 + brow)*72 + ks*16 + bcol)*2);
                u32 bhi[2], blo[2];
                ldmx2(bhi, khiA + boff);
                ldmx2(blo, kloA + boff);
                #pragma unroll
                for (int mt = 0; mt < 2; mt++) {
                    mma16816(C[mt][nt], ahi[mt], bhi);
                    mma16816(C[mt][nt], ahi[mt], blo);
                    mma16816(C[mt][nt], alo[mt], bhi);
                }
            }
        }

        // ---- p = mask * silu(s*SCALE) * gsv, written to p_sh[row][key] ----
        {
            int kbw = (w < 2) ? kb0 : kb1;
            bool tok = (w < 2) ? true : has1;
            bool diag = (kbw == qb);
            #pragma unroll
            for (int mt = 0; mt < 2; mt++) {
                #pragma unroll
                for (int nt = 0; nt < 2; nt++) {
                    int jl = 16*w + 8*nt + 2*t4;
                    int jt = jl & 31;
                    #pragma unroll
                    for (int hf = 0; hf < 2; hf++) {
                        int r = mt*16 + g4 + hf*8;
                        int jmax = diag ? r : 31;
                        bool selr = tok && ((selm_sh[r] >> kbw) & 1u);
                        float gv = gsv_sh[r];
                        float c0 = C[mt][nt][hf*2 + 0];
                        float c1 = C[mt][nt][hf*2 + 1];
                        float2 pp;
                        pp.x = (selr && (jt     <= jmax)) ? siluf(c0*SCALE)*gv : 0.f;
                        pp.y = (selr && (jt + 1 <= jmax)) ? siluf(c1*SCALE)*gv : 0.f;
                        *(float2*)&p_sh[r*64 + jl] = pp;
                    }
                }
            }
        }
        __syncthreads();   // p from all warps visible

        // ---- PV scalar fp32 (per-warp skip) ----
        bool need0 = (wsel >> kb0) & 1u;
        bool need1 = has1 && ((wsel >> kb1) & 1u);
        if (need0) {
            #pragma unroll
            for (int j4 = 0; j4 < 8; j4++) {
                u64 v[4];
                #pragma unroll
                for (int jj = 0; jj < 4; jj++) v[jj] = vbU[(j4*4 + jj)*32 + lane];
                #pragma unroll
                for (int qi = 0; qi < 8; qi++) {
                    float4 pb = p4[(w + qi*4)*16 + j4];
                    acc[qi] = ffma2(dup2(pb.x), v[0], acc[qi]);
                    acc[qi] = ffma2(dup2(pb.y), v[1], acc[qi]);
                    acc[qi] = ffma2(dup2(pb.z), v[2], acc[qi]);
                    acc[qi] = ffma2(dup2(pb.w), v[3], acc[qi]);
                }
            }
        }
        if (need1) {
            #pragma unroll
            for (int j4 = 8; j4 < 16; j4++) {
                u64 v[4];
                #pragma unroll
                for (int jj = 0; jj < 4; jj++) v[jj] = vbU[(j4*4 + jj)*32 + lane];
                #pragma unroll
                for (int qi = 0; qi < 8; qi++) {
                    float4 pb = p4[(w + qi*4)*16 + j4];
                    acc[qi] = ffma2(dup2(pb.x), v[0], acc[qi]);
                    acc[qi] = ffma2(dup2(pb.y), v[1], acc[qi]);
                    acc[qi] = ffma2(dup2(pb.z), v[2], acc[qi]);
                    acc[qi] = ffma2(dup2(pb.w), v[3], acc[qi]);
                }
            }
        }
        __syncthreads();   // all PV reads done before next staging
    }

    // ================= Output (already gated) =================
    #pragma unroll
    for (int qi = 0; qi < 8; qi++) {
        int r = w + qi*4;
        if (r >= nvalid) continue;   // warp-uniform
        float2 o2 = u2f2(acc[qi]);
        int n = qb*BSc + r;
        int o = ((t0 + n)*Hc + h)*Dc;
        *((float2*)(out + o) + lane) = o2;
    }
}

extern "C" void kernel_launch(void* const* d_in, const int* in_sizes, int n_in,
                              void* d_out, int out_size) {
    const float* pq   = (const float*)d_in[4];
    const float* pk   = (const float*)d_in[5];
    const float* pv   = (const float*)d_in[6];
    const int*   xoff = (const int*)d_in[7];
    const float* gw   = (const float*)d_in[8];
    float* out = (float*)d_out;

    static int configured = 0;
    if (!configured) {
        cudaFuncSetAttribute(hstu_main,
                             cudaFuncAttributeMaxDynamicSharedMemorySize, SMEM_TOT);
        configured = 1;
    }

    meanKV<<<Bc*NBc*Hc, 64>>>(pk, pv);
    splitQK<<<TOT/256, 256>>>(pq, pk);
    dim3 grid(NBc, Hc, Bc);
    hstu_main<<<grid, 128, SMEM_TOT>>>(pq, pv, gw, xoff, out);
}